// round 14
// baseline (speedup 1.0000x reference)
#include <cuda_runtime.h>

// QuantumOperator — FINAL (champion; reproduced 84.45/84.48/84.77/84.45 us).
//
// Key optimization (R0): algebraic collapse of the operator.
//   op_real = p p^T + diag(sigmoid(p) - p^2),  op_imag = p 1^T - 1 p^T
//   =>  with a_r = sr.p, a_i = si.p, s_r = sum(sr), s_i = sum(si),
//       d_j = sigmoid(p_j) - p_j^2:
//   out_real[j] = (a_r + s_i) * p_j + d_j * sr[j] - a_i
//   out_imag[j] = (a_i - s_r) * p_j + d_j * si[j] + a_r
//
// Turns a 34 GFLOP complex GEMM into 537 MB of pure streaming — the
// information-theoretic traffic floor. Ten config sweeps (occupancy, MLP,
// layout, TMA/bulk read+write paths, cache hints, wave shape, burst length)
// all converge on ~6.2 TB/s = the practical mixed 50/50 R/W HBM3e ceiling on
// this part; this kernel sits on that roofline (537 MB / 6.2 TB/s ~= 78 us
// measured kernel time).
//
// Config: 4-row batch, 8x LDG.128 (__ldcg) read burst, 16 parallel butterfly
// reduction chains, 8x STG.128 (__stcs) write burst, interleaved grid-stride,
// 2048 blocks x 256 threads.

#define DIM 128

__device__ __forceinline__ float dot4(const float4 a, const float4 b) {
    return a.x * b.x + a.y * b.y + a.z * b.z + a.w * b.w;
}
__device__ __forceinline__ float hsum4(const float4 a) {
    return a.x + a.y + a.z + a.w;
}

__global__ void __launch_bounds__(256) quantum_op_kernel(
    const float4* __restrict__ srv,
    const float4* __restrict__ siv,
    const float* __restrict__ p,
    float4* __restrict__ out_real,
    float4* __restrict__ out_imag,
    int M)
{
    const int lane = threadIdx.x & 31;
    const int warp = blockIdx.x * (blockDim.x >> 5) + (threadIdx.x >> 5);
    const int nwarps = gridDim.x * (blockDim.x >> 5);

    const float4 p4 = reinterpret_cast<const float4*>(p)[lane];
    float4 d4;
    d4.x = 1.0f / (1.0f + __expf(-p4.x)) - p4.x * p4.x;
    d4.y = 1.0f / (1.0f + __expf(-p4.y)) - p4.y * p4.y;
    d4.z = 1.0f / (1.0f + __expf(-p4.z)) - p4.z * p4.z;
    d4.w = 1.0f / (1.0f + __expf(-p4.w)) - p4.w * p4.w;

    const int stride = nwarps * 4;

    for (int row = warp * 4; row < M; row += stride) {
        const size_t base = (size_t)row * 32 + lane;

        // ---- 8x LDG.128 back-to-back: 4KB read burst per warp ----
        const float4 a0 = __ldcg(&srv[base]);
        const float4 a1 = __ldcg(&srv[base + 32]);
        const float4 a2 = __ldcg(&srv[base + 64]);
        const float4 a3 = __ldcg(&srv[base + 96]);
        const float4 b0 = __ldcg(&siv[base]);
        const float4 b1 = __ldcg(&siv[base + 32]);
        const float4 b2 = __ldcg(&siv[base + 64]);
        const float4 b3 = __ldcg(&siv[base + 96]);

        // ---- 16 independent butterfly chains ----
        float ar0 = dot4(a0, p4), ai0 = dot4(b0, p4), sr0 = hsum4(a0), si0 = hsum4(b0);
        float ar1 = dot4(a1, p4), ai1 = dot4(b1, p4), sr1 = hsum4(a1), si1 = hsum4(b1);
        float ar2 = dot4(a2, p4), ai2 = dot4(b2, p4), sr2 = hsum4(a2), si2 = hsum4(b2);
        float ar3 = dot4(a3, p4), ai3 = dot4(b3, p4), sr3 = hsum4(a3), si3 = hsum4(b3);

        #pragma unroll
        for (int off = 16; off > 0; off >>= 1) {
            ar0 += __shfl_xor_sync(0xFFFFFFFFu, ar0, off);
            ai0 += __shfl_xor_sync(0xFFFFFFFFu, ai0, off);
            sr0 += __shfl_xor_sync(0xFFFFFFFFu, sr0, off);
            si0 += __shfl_xor_sync(0xFFFFFFFFu, si0, off);
            ar1 += __shfl_xor_sync(0xFFFFFFFFu, ar1, off);
            ai1 += __shfl_xor_sync(0xFFFFFFFFu, ai1, off);
            sr1 += __shfl_xor_sync(0xFFFFFFFFu, sr1, off);
            si1 += __shfl_xor_sync(0xFFFFFFFFu, si1, off);
            ar2 += __shfl_xor_sync(0xFFFFFFFFu, ar2, off);
            ai2 += __shfl_xor_sync(0xFFFFFFFFu, ai2, off);
            sr2 += __shfl_xor_sync(0xFFFFFFFFu, sr2, off);
            si2 += __shfl_xor_sync(0xFFFFFFFFu, si2, off);
            ar3 += __shfl_xor_sync(0xFFFFFFFFu, ar3, off);
            ai3 += __shfl_xor_sync(0xFFFFFFFFu, ai3, off);
            sr3 += __shfl_xor_sync(0xFFFFFFFFu, sr3, off);
            si3 += __shfl_xor_sync(0xFFFFFFFFu, si3, off);
        }

        float4 or0, or1, or2, or3, oi0, oi1, oi2, oi3;
        {
            const float cr = ar0 + si0, ci = ai0 - sr0;
            or0.x = cr * p4.x + d4.x * a0.x - ai0;
            or0.y = cr * p4.y + d4.y * a0.y - ai0;
            or0.z = cr * p4.z + d4.z * a0.z - ai0;
            or0.w = cr * p4.w + d4.w * a0.w - ai0;
            oi0.x = ci * p4.x + d4.x * b0.x + ar0;
            oi0.y = ci * p4.y + d4.y * b0.y + ar0;
            oi0.z = ci * p4.z + d4.z * b0.z + ar0;
            oi0.w = ci * p4.w + d4.w * b0.w + ar0;
        }
        {
            const float cr = ar1 + si1, ci = ai1 - sr1;
            or1.x = cr * p4.x + d4.x * a1.x - ai1;
            or1.y = cr * p4.y + d4.y * a1.y - ai1;
            or1.z = cr * p4.z + d4.z * a1.z - ai1;
            or1.w = cr * p4.w + d4.w * a1.w - ai1;
            oi1.x = ci * p4.x + d4.x * b1.x + ar1;
            oi1.y = ci * p4.y + d4.y * b1.y + ar1;
            oi1.z = ci * p4.z + d4.z * b1.z + ar1;
            oi1.w = ci * p4.w + d4.w * b1.w + ar1;
        }
        {
            const float cr = ar2 + si2, ci = ai2 - sr2;
            or2.x = cr * p4.x + d4.x * a2.x - ai2;
            or2.y = cr * p4.y + d4.y * a2.y - ai2;
            or2.z = cr * p4.z + d4.z * a2.z - ai2;
            or2.w = cr * p4.w + d4.w * a2.w - ai2;
            oi2.x = ci * p4.x + d4.x * b2.x + ar2;
            oi2.y = ci * p4.y + d4.y * b2.y + ar2;
            oi2.z = ci * p4.z + d4.z * b2.z + ar2;
            oi2.w = ci * p4.w + d4.w * b2.w + ar2;
        }
        {
            const float cr = ar3 + si3, ci = ai3 - sr3;
            or3.x = cr * p4.x + d4.x * a3.x - ai3;
            or3.y = cr * p4.y + d4.y * a3.y - ai3;
            or3.z = cr * p4.z + d4.z * a3.z - ai3;
            or3.w = cr * p4.w + d4.w * a3.w - ai3;
            oi3.x = ci * p4.x + d4.x * b3.x + ar3;
            oi3.y = ci * p4.y + d4.y * b3.y + ar3;
            oi3.z = ci * p4.z + d4.z * b3.z + ar3;
            oi3.w = ci * p4.w + d4.w * b3.w + ar3;
        }

        __stcs(&out_real[base],      or0);
        __stcs(&out_real[base + 32], or1);
        __stcs(&out_real[base + 64], or2);
        __stcs(&out_real[base + 96], or3);
        __stcs(&out_imag[base],      oi0);
        __stcs(&out_imag[base + 32], oi1);
        __stcs(&out_imag[base + 64], oi2);
        __stcs(&out_imag[base + 96], oi3);
    }
}

extern "C" void kernel_launch(void* const* d_in, const int* in_sizes, int n_in,
                              void* d_out, int out_size) {
    const float* sr = (const float*)d_in[0];
    const float* si = (const float*)d_in[1];
    const float* p  = (const float*)d_in[2];
    float* out = (float*)d_out;

    const int M = in_sizes[0] / DIM;                 // 262144 rows
    float4* out_real = (float4*)out;
    float4* out_imag = (float4*)(out + (size_t)M * DIM);

    const int threads = 256;
    const int blocks = 2048;                         // champion config
    quantum_op_kernel<<<blocks, threads>>>(
        (const float4*)sr, (const float4*)si, p, out_real, out_imag, M);
}

// round 15
// speedup vs baseline: 1.0034x; 1.0034x over previous
#include <cuda_runtime.h>

// QuantumOperator — FINAL (champion; reproduced 84.45/84.48/84.77/84.45/84.99 us).
//
// Key optimization (R0): algebraic collapse of the operator.
//   op_real = p p^T + diag(sigmoid(p) - p^2),  op_imag = p 1^T - 1 p^T
//   =>  with a_r = sr.p, a_i = si.p, s_r = sum(sr), s_i = sum(si),
//       d_j = sigmoid(p_j) - p_j^2:
//   out_real[j] = (a_r + s_i) * p_j + d_j * sr[j] - a_i
//   out_imag[j] = (a_i - s_r) * p_j + d_j * si[j] + a_r
//
// Turns a 34 GFLOP complex GEMM into 537 MB of pure streaming — the
// information-theoretic traffic floor. Ten config sweeps (occupancy, MLP,
// layout, TMA/bulk read+write paths, cache hints, wave shape, burst length)
// all converge on ~6.2 TB/s = the practical mixed 50/50 R/W HBM3e ceiling on
// this part; this kernel sits on that roofline (537 MB / 6.2 TB/s ~= 78 us
// measured kernel time).
//
// Config: 4-row batch, 8x LDG.128 (__ldcg) read burst, 16 parallel butterfly
// reduction chains, 8x STG.128 (__stcs) write burst, interleaved grid-stride,
// 2048 blocks x 256 threads.

#define DIM 128

__device__ __forceinline__ float dot4(const float4 a, const float4 b) {
    return a.x * b.x + a.y * b.y + a.z * b.z + a.w * b.w;
}
__device__ __forceinline__ float hsum4(const float4 a) {
    return a.x + a.y + a.z + a.w;
}

__global__ void __launch_bounds__(256) quantum_op_kernel(
    const float4* __restrict__ srv,
    const float4* __restrict__ siv,
    const float* __restrict__ p,
    float4* __restrict__ out_real,
    float4* __restrict__ out_imag,
    int M)
{
    const int lane = threadIdx.x & 31;
    const int warp = blockIdx.x * (blockDim.x >> 5) + (threadIdx.x >> 5);
    const int nwarps = gridDim.x * (blockDim.x >> 5);

    const float4 p4 = reinterpret_cast<const float4*>(p)[lane];
    float4 d4;
    d4.x = 1.0f / (1.0f + __expf(-p4.x)) - p4.x * p4.x;
    d4.y = 1.0f / (1.0f + __expf(-p4.y)) - p4.y * p4.y;
    d4.z = 1.0f / (1.0f + __expf(-p4.z)) - p4.z * p4.z;
    d4.w = 1.0f / (1.0f + __expf(-p4.w)) - p4.w * p4.w;

    const int stride = nwarps * 4;

    for (int row = warp * 4; row < M; row += stride) {
        const size_t base = (size_t)row * 32 + lane;

        // ---- 8x LDG.128 back-to-back: 4KB read burst per warp ----
        const float4 a0 = __ldcg(&srv[base]);
        const float4 a1 = __ldcg(&srv[base + 32]);
        const float4 a2 = __ldcg(&srv[base + 64]);
        const float4 a3 = __ldcg(&srv[base + 96]);
        const float4 b0 = __ldcg(&siv[base]);
        const float4 b1 = __ldcg(&siv[base + 32]);
        const float4 b2 = __ldcg(&siv[base + 64]);
        const float4 b3 = __ldcg(&siv[base + 96]);

        // ---- 16 independent butterfly chains ----
        float ar0 = dot4(a0, p4), ai0 = dot4(b0, p4), sr0 = hsum4(a0), si0 = hsum4(b0);
        float ar1 = dot4(a1, p4), ai1 = dot4(b1, p4), sr1 = hsum4(a1), si1 = hsum4(b1);
        float ar2 = dot4(a2, p4), ai2 = dot4(b2, p4), sr2 = hsum4(a2), si2 = hsum4(b2);
        float ar3 = dot4(a3, p4), ai3 = dot4(b3, p4), sr3 = hsum4(a3), si3 = hsum4(b3);

        #pragma unroll
        for (int off = 16; off > 0; off >>= 1) {
            ar0 += __shfl_xor_sync(0xFFFFFFFFu, ar0, off);
            ai0 += __shfl_xor_sync(0xFFFFFFFFu, ai0, off);
            sr0 += __shfl_xor_sync(0xFFFFFFFFu, sr0, off);
            si0 += __shfl_xor_sync(0xFFFFFFFFu, si0, off);
            ar1 += __shfl_xor_sync(0xFFFFFFFFu, ar1, off);
            ai1 += __shfl_xor_sync(0xFFFFFFFFu, ai1, off);
            sr1 += __shfl_xor_sync(0xFFFFFFFFu, sr1, off);
            si1 += __shfl_xor_sync(0xFFFFFFFFu, si1, off);
            ar2 += __shfl_xor_sync(0xFFFFFFFFu, ar2, off);
            ai2 += __shfl_xor_sync(0xFFFFFFFFu, ai2, off);
            sr2 += __shfl_xor_sync(0xFFFFFFFFu, sr2, off);
            si2 += __shfl_xor_sync(0xFFFFFFFFu, si2, off);
            ar3 += __shfl_xor_sync(0xFFFFFFFFu, ar3, off);
            ai3 += __shfl_xor_sync(0xFFFFFFFFu, ai3, off);
            sr3 += __shfl_xor_sync(0xFFFFFFFFu, sr3, off);
            si3 += __shfl_xor_sync(0xFFFFFFFFu, si3, off);
        }

        float4 or0, or1, or2, or3, oi0, oi1, oi2, oi3;
        {
            const float cr = ar0 + si0, ci = ai0 - sr0;
            or0.x = cr * p4.x + d4.x * a0.x - ai0;
            or0.y = cr * p4.y + d4.y * a0.y - ai0;
            or0.z = cr * p4.z + d4.z * a0.z - ai0;
            or0.w = cr * p4.w + d4.w * a0.w - ai0;
            oi0.x = ci * p4.x + d4.x * b0.x + ar0;
            oi0.y = ci * p4.y + d4.y * b0.y + ar0;
            oi0.z = ci * p4.z + d4.z * b0.z + ar0;
            oi0.w = ci * p4.w + d4.w * b0.w + ar0;
        }
        {
            const float cr = ar1 + si1, ci = ai1 - sr1;
            or1.x = cr * p4.x + d4.x * a1.x - ai1;
            or1.y = cr * p4.y + d4.y * a1.y - ai1;
            or1.z = cr * p4.z + d4.z * a1.z - ai1;
            or1.w = cr * p4.w + d4.w * a1.w - ai1;
            oi1.x = ci * p4.x + d4.x * b1.x + ar1;
            oi1.y = ci * p4.y + d4.y * b1.y + ar1;
            oi1.z = ci * p4.z + d4.z * b1.z + ar1;
            oi1.w = ci * p4.w + d4.w * b1.w + ar1;
        }
        {
            const float cr = ar2 + si2, ci = ai2 - sr2;
            or2.x = cr * p4.x + d4.x * a2.x - ai2;
            or2.y = cr * p4.y + d4.y * a2.y - ai2;
            or2.z = cr * p4.z + d4.z * a2.z - ai2;
            or2.w = cr * p4.w + d4.w * a2.w - ai2;
            oi2.x = ci * p4.x + d4.x * b2.x + ar2;
            oi2.y = ci * p4.y + d4.y * b2.y + ar2;
            oi2.z = ci * p4.z + d4.z * b2.z + ar2;
            oi2.w = ci * p4.w + d4.w * b2.w + ar2;
        }
        {
            const float cr = ar3 + si3, ci = ai3 - sr3;
            or3.x = cr * p4.x + d4.x * a3.x - ai3;
            or3.y = cr * p4.y + d4.y * a3.y - ai3;
            or3.z = cr * p4.z + d4.z * a3.z - ai3;
            or3.w = cr * p4.w + d4.w * a3.w - ai3;
            oi3.x = ci * p4.x + d4.x * b3.x + ar3;
            oi3.y = ci * p4.y + d4.y * b3.y + ar3;
            oi3.z = ci * p4.z + d4.z * b3.z + ar3;
            oi3.w = ci * p4.w + d4.w * b3.w + ar3;
        }

        __stcs(&out_real[base],      or0);
        __stcs(&out_real[base + 32], or1);
        __stcs(&out_real[base + 64], or2);
        __stcs(&out_real[base + 96], or3);
        __stcs(&out_imag[base],      oi0);
        __stcs(&out_imag[base + 32], oi1);
        __stcs(&out_imag[base + 64], oi2);
        __stcs(&out_imag[base + 96], oi3);
    }
}

extern "C" void kernel_launch(void* const* d_in, const int* in_sizes, int n_in,
                              void* d_out, int out_size) {
    const float* sr = (const float*)d_in[0];
    const float* si = (const float*)d_in[1];
    const float* p  = (const float*)d_in[2];
    float* out = (float*)d_out;

    const int M = in_sizes[0] / DIM;                 // 262144 rows
    float4* out_real = (float4*)out;
    float4* out_imag = (float4*)(out + (size_t)M * DIM);

    const int threads = 256;
    const int blocks = 2048;                         // champion config
    quantum_op_kernel<<<blocks, threads>>>(
        (const float4*)sr, (const float4*)si, p, out_real, out_imag, M);
}

// round 17
// speedup vs baseline: 1.0064x; 1.0030x over previous
#include <cuda_runtime.h>

// QuantumOperator — FINAL (champion; 6 reproductions, mean 84.6 us, sigma 0.2).
//
// Key optimization (R0): algebraic collapse of the operator.
//   op_real = p p^T + diag(sigmoid(p) - p^2),  op_imag = p 1^T - 1 p^T
//   =>  with a_r = sr.p, a_i = si.p, s_r = sum(sr), s_i = sum(si),
//       d_j = sigmoid(p_j) - p_j^2:
//   out_real[j] = (a_r + s_i) * p_j + d_j * sr[j] - a_i
//   out_imag[j] = (a_i - s_r) * p_j + d_j * si[j] + a_r
//
// Turns a 34 GFLOP complex GEMM into 537 MB of pure streaming — the
// information-theoretic traffic floor. Ten config sweeps (occupancy, MLP,
// layout, TMA/bulk read+write paths, cache hints, wave shape, burst length)
// all converge on ~6.2 TB/s = the practical mixed 50/50 R/W HBM3e ceiling on
// this part; this kernel sits on that roofline (537 MB / 6.2 TB/s ~= 78 us
// measured kernel time). redux.sync.add.f32 was also tried (R16) and is not
// supported by ptxas on sm_103a — SHFL butterflies stay.
//
// Config: 4-row batch, 8x LDG.128 (__ldcg) read burst, 16 parallel butterfly
// reduction chains, 8x STG.128 (__stcs) write burst, interleaved grid-stride,
// 2048 blocks x 256 threads.

#define DIM 128

__device__ __forceinline__ float dot4(const float4 a, const float4 b) {
    return a.x * b.x + a.y * b.y + a.z * b.z + a.w * b.w;
}
__device__ __forceinline__ float hsum4(const float4 a) {
    return a.x + a.y + a.z + a.w;
}

__global__ void __launch_bounds__(256) quantum_op_kernel(
    const float4* __restrict__ srv,
    const float4* __restrict__ siv,
    const float* __restrict__ p,
    float4* __restrict__ out_real,
    float4* __restrict__ out_imag,
    int M)
{
    const int lane = threadIdx.x & 31;
    const int warp = blockIdx.x * (blockDim.x >> 5) + (threadIdx.x >> 5);
    const int nwarps = gridDim.x * (blockDim.x >> 5);

    const float4 p4 = reinterpret_cast<const float4*>(p)[lane];
    float4 d4;
    d4.x = 1.0f / (1.0f + __expf(-p4.x)) - p4.x * p4.x;
    d4.y = 1.0f / (1.0f + __expf(-p4.y)) - p4.y * p4.y;
    d4.z = 1.0f / (1.0f + __expf(-p4.z)) - p4.z * p4.z;
    d4.w = 1.0f / (1.0f + __expf(-p4.w)) - p4.w * p4.w;

    const int stride = nwarps * 4;

    for (int row = warp * 4; row < M; row += stride) {
        const size_t base = (size_t)row * 32 + lane;

        // ---- 8x LDG.128 back-to-back: 4KB read burst per warp ----
        const float4 a0 = __ldcg(&srv[base]);
        const float4 a1 = __ldcg(&srv[base + 32]);
        const float4 a2 = __ldcg(&srv[base + 64]);
        const float4 a3 = __ldcg(&srv[base + 96]);
        const float4 b0 = __ldcg(&siv[base]);
        const float4 b1 = __ldcg(&siv[base + 32]);
        const float4 b2 = __ldcg(&siv[base + 64]);
        const float4 b3 = __ldcg(&siv[base + 96]);

        // ---- 16 independent butterfly chains ----
        float ar0 = dot4(a0, p4), ai0 = dot4(b0, p4), sr0 = hsum4(a0), si0 = hsum4(b0);
        float ar1 = dot4(a1, p4), ai1 = dot4(b1, p4), sr1 = hsum4(a1), si1 = hsum4(b1);
        float ar2 = dot4(a2, p4), ai2 = dot4(b2, p4), sr2 = hsum4(a2), si2 = hsum4(b2);
        float ar3 = dot4(a3, p4), ai3 = dot4(b3, p4), sr3 = hsum4(a3), si3 = hsum4(b3);

        #pragma unroll
        for (int off = 16; off > 0; off >>= 1) {
            ar0 += __shfl_xor_sync(0xFFFFFFFFu, ar0, off);
            ai0 += __shfl_xor_sync(0xFFFFFFFFu, ai0, off);
            sr0 += __shfl_xor_sync(0xFFFFFFFFu, sr0, off);
            si0 += __shfl_xor_sync(0xFFFFFFFFu, si0, off);
            ar1 += __shfl_xor_sync(0xFFFFFFFFu, ar1, off);
            ai1 += __shfl_xor_sync(0xFFFFFFFFu, ai1, off);
            sr1 += __shfl_xor_sync(0xFFFFFFFFu, sr1, off);
            si1 += __shfl_xor_sync(0xFFFFFFFFu, si1, off);
            ar2 += __shfl_xor_sync(0xFFFFFFFFu, ar2, off);
            ai2 += __shfl_xor_sync(0xFFFFFFFFu, ai2, off);
            sr2 += __shfl_xor_sync(0xFFFFFFFFu, sr2, off);
            si2 += __shfl_xor_sync(0xFFFFFFFFu, si2, off);
            ar3 += __shfl_xor_sync(0xFFFFFFFFu, ar3, off);
            ai3 += __shfl_xor_sync(0xFFFFFFFFu, ai3, off);
            sr3 += __shfl_xor_sync(0xFFFFFFFFu, sr3, off);
            si3 += __shfl_xor_sync(0xFFFFFFFFu, si3, off);
        }

        float4 or0, or1, or2, or3, oi0, oi1, oi2, oi3;
        {
            const float cr = ar0 + si0, ci = ai0 - sr0;
            or0.x = cr * p4.x + d4.x * a0.x - ai0;
            or0.y = cr * p4.y + d4.y * a0.y - ai0;
            or0.z = cr * p4.z + d4.z * a0.z - ai0;
            or0.w = cr * p4.w + d4.w * a0.w - ai0;
            oi0.x = ci * p4.x + d4.x * b0.x + ar0;
            oi0.y = ci * p4.y + d4.y * b0.y + ar0;
            oi0.z = ci * p4.z + d4.z * b0.z + ar0;
            oi0.w = ci * p4.w + d4.w * b0.w + ar0;
        }
        {
            const float cr = ar1 + si1, ci = ai1 - sr1;
            or1.x = cr * p4.x + d4.x * a1.x - ai1;
            or1.y = cr * p4.y + d4.y * a1.y - ai1;
            or1.z = cr * p4.z + d4.z * a1.z - ai1;
            or1.w = cr * p4.w + d4.w * a1.w - ai1;
            oi1.x = ci * p4.x + d4.x * b1.x + ar1;
            oi1.y = ci * p4.y + d4.y * b1.y + ar1;
            oi1.z = ci * p4.z + d4.z * b1.z + ar1;
            oi1.w = ci * p4.w + d4.w * b1.w + ar1;
        }
        {
            const float cr = ar2 + si2, ci = ai2 - sr2;
            or2.x = cr * p4.x + d4.x * a2.x - ai2;
            or2.y = cr * p4.y + d4.y * a2.y - ai2;
            or2.z = cr * p4.z + d4.z * a2.z - ai2;
            or2.w = cr * p4.w + d4.w * a2.w - ai2;
            oi2.x = ci * p4.x + d4.x * b2.x + ar2;
            oi2.y = ci * p4.y + d4.y * b2.y + ar2;
            oi2.z = ci * p4.z + d4.z * b2.z + ar2;
            oi2.w = ci * p4.w + d4.w * b2.w + ar2;
        }
        {
            const float cr = ar3 + si3, ci = ai3 - sr3;
            or3.x = cr * p4.x + d4.x * a3.x - ai3;
            or3.y = cr * p4.y + d4.y * a3.y - ai3;
            or3.z = cr * p4.z + d4.z * a3.z - ai3;
            or3.w = cr * p4.w + d4.w * a3.w - ai3;
            oi3.x = ci * p4.x + d4.x * b3.x + ar3;
            oi3.y = ci * p4.y + d4.y * b3.y + ar3;
            oi3.z = ci * p4.z + d4.z * b3.z + ar3;
            oi3.w = ci * p4.w + d4.w * b3.w + ar3;
        }

        __stcs(&out_real[base],      or0);
        __stcs(&out_real[base + 32], or1);
        __stcs(&out_real[base + 64], or2);
        __stcs(&out_real[base + 96], or3);
        __stcs(&out_imag[base],      oi0);
        __stcs(&out_imag[base + 32], oi1);
        __stcs(&out_imag[base + 64], oi2);
        __stcs(&out_imag[base + 96], oi3);
    }
}

extern "C" void kernel_launch(void* const* d_in, const int* in_sizes, int n_in,
                              void* d_out, int out_size) {
    const float* sr = (const float*)d_in[0];
    const float* si = (const float*)d_in[1];
    const float* p  = (const float*)d_in[2];
    float* out = (float*)d_out;

    const int M = in_sizes[0] / DIM;                 // 262144 rows
    float4* out_real = (float4*)out;
    float4* out_imag = (float4*)(out + (size_t)M * DIM);

    const int threads = 256;
    const int blocks = 2048;                         // champion config
    quantum_op_kernel<<<blocks, threads>>>(
        (const float4*)sr, (const float4*)si, p, out_real, out_imag, M);
}